// round 15
// baseline (speedup 1.0000x reference)
#include <cuda_runtime.h>
#include <cuda_fp16.h>
#include <cstdint>

// ============================================================================
// TaylorLinearNet2 via HMMA (mma.sync fp16), portable sm_100 target.
//   t = X @ W^T  (M=4096, N=8192, K=1024), then per-8-col Taylor epilogue.
// Pure fp16 operands (calibrated rel_err 2.63e-4 << 1e-3).
// Round 15: PAIRED iterations — one CP_WAIT + one __syncthreads per TWO BK=32
//   stages (sync events 32 -> 16/CTA). Cycle ledger: MMA floor 1024 cyc/iter
//   (= tensor 52.4% measured) + ~900 cyc inter-iteration sync overhead; halving
//   sync frequency targets that overhead. STAGES=6, fragment rotation kept.
// ============================================================================

#define M_TOTAL 4096
#define N_TOTAL 8192
#define K_IN    1024
#define ODIM    1024

#define BM 128
#define BN 256
#define BK 32
#define STAGES 6
#define NCH (K_IN / BK)         // 32
#define NPAIR (NCH / 2)         // 16

// smem rows: 32 fp16 data (64B) + 16B pad = 80 B; row r starts bank (20r mod 32)
#define ROWB 80
#define A_BYTES (BM * ROWB)             // 10240
#define B_BYTES (BN * ROWB)             // 20480
#define STAGE_BYTES (A_BYTES + B_BYTES) // 30720
#define SMEM_TOTAL (STAGES * STAGE_BYTES) // 184320

__device__ __align__(128) __half g_A[(size_t)M_TOTAL * K_IN]; // 8 MB
__device__ __align__(128) __half g_B[(size_t)N_TOTAL * K_IN]; // 16 MB

__device__ __forceinline__ uint32_t smem_u32(const void* p) {
    uint32_t a;
    asm("{ .reg .u64 t; cvta.to.shared.u64 t, %1; cvt.u32.u64 %0, t; }"
        : "=r"(a) : "l"(p));
    return a;
}

#define CP_ASYNC16(dst, src) \
    asm volatile("cp.async.cg.shared.global [%0], [%1], 16;" :: "r"(dst), "l"(src))
#define CP_COMMIT() asm volatile("cp.async.commit_group;" ::: "memory")
#define CP_WAIT(n)  asm volatile("cp.async.wait_group %0;" :: "n"(n) : "memory")

#define LDMATRIX_X4(r0, r1, r2, r3, addr) \
    asm volatile("ldmatrix.sync.aligned.m8n8.x4.shared.b16 {%0,%1,%2,%3}, [%4];" \
                 : "=r"(r0), "=r"(r1), "=r"(r2), "=r"(r3) : "r"(addr))

#define MMA_F16(acc, a, b0v, b1v) \
    asm volatile("mma.sync.aligned.m16n8k16.row.col.f32.f16.f16.f32 " \
                 "{%0,%1,%2,%3}, {%4,%5,%6,%7}, {%8,%9}, {%0,%1,%2,%3};" \
                 : "+f"((acc)[0]), "+f"((acc)[1]), "+f"((acc)[2]), "+f"((acc)[3]) \
                 : "r"((a)[0]), "r"((a)[1]), "r"((a)[2]), "r"((a)[3]), \
                   "r"(b0v), "r"(b1v))

// One k16-step: prefetch bf[bn] + af from the NEXT k-step location naddr,
// MMA with bf[bc] + current af. (af reload ordered after its consumers.)
#define K_STEP(bc, bn, naddr) do {                                            \
    _Pragma("unroll")                                                         \
    for (int np = 0; np < 4; np++)                                            \
        LDMATRIX_X4(bf[bn][np][0], bf[bn][np][1], bf[bn][np][2], bf[bn][np][3], \
                    (naddr) + bOff + np * 16 * ROWB);                         \
    _Pragma("unroll")                                                         \
    for (int mt = 0; mt < 2; mt++)                                            \
        _Pragma("unroll")                                                     \
        for (int nt = 0; nt < 8; nt++)                                        \
            MMA_F16(acc[mt][nt], af[mt],                                      \
                    bf[bc][nt >> 1][(nt & 1) * 2],                            \
                    bf[bc][nt >> 1][(nt & 1) * 2 + 1]);                       \
    _Pragma("unroll")                                                         \
    for (int mt = 0; mt < 2; mt++)                                            \
        LDMATRIX_X4(af[mt][0], af[mt][1], af[mt][2], af[mt][3],               \
                    (naddr) + aOff + mt * 16 * ROWB);                         \
} while (0)

// ============================================================================
// merged conversion kernel (round-10, measured good): 16 elems/thread, MLP=4
// ============================================================================
__device__ __forceinline__ uint32_t hpack2(float a, float b) {
    __half2 h; h.x = __float2half_rn(a); h.y = __float2half_rn(b);
    return *reinterpret_cast<uint32_t*>(&h);
}

__device__ __forceinline__ void cvt16(const float* __restrict__ src,
                                      __half* __restrict__ dst, size_t base) {
    const float4* s4 = reinterpret_cast<const float4*>(src + base);
    float4 v0 = s4[0], v1 = s4[1], v2 = s4[2], v3 = s4[3];   // 4-wide MLP
    uint4 h0, h1;
    h0.x = hpack2(v0.x, v0.y);  h0.y = hpack2(v0.z, v0.w);
    h0.z = hpack2(v1.x, v1.y);  h0.w = hpack2(v1.z, v1.w);
    h1.x = hpack2(v2.x, v2.y);  h1.y = hpack2(v2.z, v2.w);
    h1.z = hpack2(v3.x, v3.y);  h1.w = hpack2(v3.z, v3.w);
    *reinterpret_cast<uint4*>(dst + base)     = h0;
    *reinterpret_cast<uint4*>(dst + base + 8) = h1;
}

#define X_BLOCKS 1024   // 1024 * 256 * 16 = M*K
#define W_BLOCKS 2048   // 2048 * 256 * 16 = N*K

__global__ void convert_kernel(const float* __restrict__ X,
                               const float* __restrict__ W) {
    if (blockIdx.x < X_BLOCKS) {
        size_t base = ((size_t)blockIdx.x * 256 + threadIdx.x) * 16;
        cvt16(X, g_A, base);
    } else {
        size_t base = ((size_t)(blockIdx.x - X_BLOCKS) * 256 + threadIdx.x) * 16;
        cvt16(W, g_B, base);
    }
}

// ============================================================================
// GEMM + fused Taylor epilogue.  grid (N/256, M/128) = (32, 32), 512 threads.
// Warp grid 4(m) x 4(n); warp tile m32 x n64.
// ============================================================================
__global__ __launch_bounds__(512, 1)
void taylor_hmma_kernel(const float* __restrict__ D0, float* __restrict__ OUT)
{
    extern __shared__ __align__(128) char smem[];
    const uint32_t sb = smem_u32(smem);

    const int tid  = threadIdx.x;
    const int lane = tid & 31;
    const int wid  = tid >> 5;
    const int warp_m = wid >> 2;    // 0..3 -> m offset *32
    const int warp_n = wid & 3;     // 0..3 -> n offset *64

    const int bm = blockIdx.y * BM;
    const int bn = blockIdx.x * BN;

    // ---- cp.async mapping: 3 x 16B per thread per stage ----
    const int grow = tid >> 2;          // 0..127
    const int gc   = tid & 3;           // 16B chunk in 64B k-slab
    const __half* gA  = g_A + (size_t)(bm + grow) * K_IN + gc * 8;
    const __half* gB0 = g_B + (size_t)(bn + grow) * K_IN + gc * 8;
    const __half* gB1 = gB0 + (size_t)128 * K_IN;
    const uint32_t sAd  = sb + grow * ROWB + gc * 16;
    const uint32_t sBd0 = sb + A_BYTES + grow * ROWB + gc * 16;
    const uint32_t sBd1 = sBd0 + 128 * ROWB;

    float acc[2][8][4];
    #pragma unroll
    for (int mt = 0; mt < 2; mt++)
        #pragma unroll
        for (int nt = 0; nt < 8; nt++)
            #pragma unroll
            for (int r = 0; r < 4; r++) acc[mt][nt][r] = 0.0f;

    // per-warp ldmatrix offsets within a stage (add stage base + ks*32)
    const uint32_t aOff = (uint32_t)((warp_m * 32 + (lane & 15)) * ROWB
                                     + (lane >> 4) * 16);
    const uint32_t bOff = (uint32_t)(A_BYTES
                        + (warp_n * 64 + (lane & 7) + ((lane >> 4) & 1) * 8) * ROWB
                        + ((lane >> 3) & 1) * 16);

    // A fragments single-buffered (rotated per k-step); B double-buffered
    uint32_t af[2][4];      // [mt][reg]
    uint32_t bf[2][4][4];   // [buf][np][reg]

    // ---- prologue: fill stages 0..3, one group each (groups 1..4) ----
    #pragma unroll
    for (int s = 0; s < 4; s++) {
        const int k0 = s * BK;
        CP_ASYNC16(sAd  + s * STAGE_BYTES, gA  + k0);
        CP_ASYNC16(sBd0 + s * STAGE_BYTES, gB0 + k0);
        CP_ASYNC16(sBd1 + s * STAGE_BYTES, gB1 + k0);
        CP_COMMIT();
    }
    CP_WAIT(3);             // stage 0 landed
    __syncthreads();        // ... and visible to all threads

    // prefetch (stage 0, ks 0): af and bf[0]
    #pragma unroll
    for (int mt = 0; mt < 2; mt++)
        LDMATRIX_X4(af[mt][0], af[mt][1], af[mt][2], af[mt][3],
                    sb + aOff + mt * 16 * ROWB);
    #pragma unroll
    for (int np = 0; np < 4; np++)
        LDMATRIX_X4(bf[0][np][0], bf[0][np][1], bf[0][np][2], bf[0][np][3],
                    sb + bOff + np * 16 * ROWB);

    int cs = 0;             // slot holding stage 2j
    int ls = 4;             // slot receiving stage 2j+4
    for (int j = 0; j < NPAIR; j++) {
        // Ledger: before pair j, 4+2j groups committed. CP_WAIT(1) lands
        // through group 3+2j = stage 2j+2 — exactly the deepest read below.
        CP_WAIT(1);
        __syncthreads();    // visibility + WAR protection for refills below
                            // (refill slots' last reads were in pair j-1)

        // refill stage 2j+4 -> slot ls  (guarded; empty commit keeps ledger)
        if (2 * j + 4 < NCH) {
            const int k0 = (2 * j + 4) * BK;
            CP_ASYNC16(sAd  + ls * STAGE_BYTES, gA  + k0);
            CP_ASYNC16(sBd0 + ls * STAGE_BYTES, gB0 + k0);
            CP_ASYNC16(sBd1 + ls * STAGE_BYTES, gB1 + k0);
        }
        CP_COMMIT();
        const int ls2 = (ls + 1 == STAGES) ? 0 : ls + 1;
        if (2 * j + 5 < NCH) {
            const int k0 = (2 * j + 5) * BK;
            CP_ASYNC16(sAd  + ls2 * STAGE_BYTES, gA  + k0);
            CP_ASYNC16(sBd0 + ls2 * STAGE_BYTES, gB0 + k0);
            CP_ASYNC16(sBd1 + ls2 * STAGE_BYTES, gB1 + k0);
        }
        CP_COMMIT();

        const uint32_t base0 = sb + cs * STAGE_BYTES;
        const int cs1 = (cs + 1 == STAGES) ? 0 : cs + 1;
        const uint32_t base1 = sb + cs1 * STAGE_BYTES;
        const int cs2 = (cs1 + 1 == STAGES) ? 0 : cs1 + 1;
        const uint32_t base2 = sb + cs2 * STAGE_BYTES;

        // 4 uninterrupted k16-steps (64 MMAs/warp), fragment rotation:
        // entering: af/bf[0] hold (stage 2j, ks0); leaving: (stage 2j+2, ks0).
        // Final pair's base2 reads are stale-but-valid smem, discarded.
        K_STEP(0, 1, base0 + 32);   // compute (2j,ks0),  fetch (2j,ks1)
        K_STEP(1, 0, base1);        // compute (2j,ks1),  fetch (2j+1,ks0)
        K_STEP(0, 1, base1 + 32);   // compute (2j+1,ks0),fetch (2j+1,ks1)
        K_STEP(1, 0, base2);        // compute (2j+1,ks1),fetch (2j+2,ks0)

        cs = cs2;
        ls = (ls2 + 1 == STAGES) ? 0 : ls2 + 1;
    }

    // ---- fused Taylor epilogue ----
    // C frag m16n8: c0,c1 -> row lane>>2, cols 2*(lane&3)+{0,1}; c2,c3 -> row+8.
    // Each n8 tile is one o-group; gather its 8 cols across the lane quad.
    const int q = lane & ~3;
    #pragma unroll
    for (int nt = 0; nt < 8; nt++) {
        const int o = blockIdx.x * 32 + warp_n * 8 + nt;
        const float d0v = D0[o];
        #pragma unroll
        for (int mt = 0; mt < 2; mt++) {
            float c0 = acc[mt][nt][0], c1 = acc[mt][nt][1];
            float c2 = acc[mt][nt][2], c3 = acc[mt][nt][3];
            float t0[8], t1[8];
            #pragma unroll
            for (int d2 = 0; d2 < 4; d2++) {
                t0[2 * d2]     = __shfl_sync(0xffffffffu, c0, q + d2);
                t0[2 * d2 + 1] = __shfl_sync(0xffffffffu, c1, q + d2);
                t1[2 * d2]     = __shfl_sync(0xffffffffu, c2, q + d2);
                t1[2 * d2 + 1] = __shfl_sync(0xffffffffu, c3, q + d2);
            }
            float p0 = t0[0], s0 = t0[0];
            float p1 = t1[0], s1 = t1[0];
            #pragma unroll
            for (int d = 1; d < 8; d++) {
                p0 *= t0[d]; s0 += p0;
                p1 *= t1[d]; s1 += p1;
            }
            if ((lane & 3) == 0) {
                const int m0 = bm + warp_m * 32 + mt * 16 + (lane >> 2);
                OUT[(size_t)m0 * ODIM + o]       = d0v + s0;
                OUT[(size_t)(m0 + 8) * ODIM + o] = d0v + s1;
            }
        }
    }
}

// ============================================================================
// host side
// ============================================================================
extern "C" void kernel_launch(void* const* d_in, const int* in_sizes, int n_in,
                              void* d_out, int out_size)
{
    const float* x  = (const float*)d_in[0];   // [4096, 1024]
    const float* wt = (const float*)d_in[1];   // [1024, 8, 1024] = [8192, 1024]
    const float* d0 = (const float*)d_in[2];   // [1, 1024]
    float* out = (float*)d_out;                // [4096, 1024]

    convert_kernel<<<X_BLOCKS + W_BLOCKS, 256>>>(x, wt);

    cudaFuncSetAttribute(taylor_hmma_kernel,
                         cudaFuncAttributeMaxDynamicSharedMemorySize, SMEM_TOTAL);
    dim3 grid(N_TOTAL / BN, M_TOTAL / BM);     // (32, 32)
    taylor_hmma_kernel<<<grid, 512, SMEM_TOTAL>>>(d0, out);
}